// round 10
// baseline (speedup 1.0000x reference)
#include <cuda_runtime.h>

#define N 4096
#define B 8
#define JT 64              // threads per block
#define JB 2               // j-columns per thread
#define JCOV (JT * JB)     // 128 j per block
#define ICH 64             // i per chunk
#define NCHUNK (N / ICH)   // 64
#define NJT (N / JCOV)     // 32

#define LOG2E 1.4426950408889634f
#define EXP_NEG1 0.36787944117144233f
// D = e - e^-1 ; fold 1/D^2 into the power scaling at the epilogue
#define DVAL 2.3504023872876028f
#define INV_D2 (1.0f / (DVAL * DVAL))
#define EPS 1e-5f

typedef unsigned long long ull;

// -------- packed f32x2 helpers --------
__device__ __forceinline__ ull pk(float lo, float hi) {
    ull r; asm("mov.b64 %0, {%1, %2};" : "=l"(r) : "f"(lo), "f"(hi)); return r;
}
__device__ __forceinline__ void upk(ull v, float& lo, float& hi) {
    asm("mov.b64 {%0, %1}, %2;" : "=f"(lo), "=f"(hi) : "l"(v));
}
__device__ __forceinline__ ull padd(ull a, ull b) {
    ull r; asm("add.rn.f32x2 %0, %1, %2;" : "=l"(r) : "l"(a), "l"(b)); return r;
}
__device__ __forceinline__ ull pmul(ull a, ull b) {
    ull r; asm("mul.rn.f32x2 %0, %1, %2;" : "=l"(r) : "l"(a), "l"(b)); return r;
}
__device__ __forceinline__ ull pfma(ull a, ull b, ull c) {
    ull r; asm("fma.rn.f32x2 %0, %1, %2, %3;" : "=l"(r) : "l"(a), "l"(b), "l"(c)); return r;
}
__device__ __forceinline__ float rsqrt_ap(float v) {
    float r; asm("rsqrt.approx.f32 %0, %1;" : "=f"(r) : "f"(v)); return r;
}
__device__ __forceinline__ float ex2_ap(float v) {
    float r; asm("ex2.approx.ftz.f32 %0, %1;" : "=f"(r) : "f"(v)); return r;
}

// -------- device scratch (no allocations allowed) --------
// partial sums: [chunk][j] -> 8 batch floats as 2 float4
__device__ float4 g_part[NCHUNK][N][2];
// per-j-tile arrival counters (zero-initialized; reset by reducing block)
__device__ int g_cnt[NJT];

// one j-column's worth of work for an i-pair (all operands in regs/smem-loaded)
__device__ __forceinline__ void do_jcol(
    const ulonglong2& q0, const ulonglong2& q1, const ulonglong2& q2,
    const ulonglong2& Xa, const ulonglong2& Xb,
    const ulonglong2& Xc, const ulonglong2& Xd,
    ull pjx2, ull pjy2, ull pjz2, ull inx2, ull iny2, ull inz2, ull cneg,
    ull& a0, ull& a1, ull& a2, ull& a3)
{
    ull dxp = padd(pjx2, q0.x);
    ull dyp = padd(pjy2, q0.y);
    ull dzp = padd(pjz2, q1.x);

    ull d2p = pfma(dxp, dxp, pfma(dyp, dyp, pmul(dzp, dzp)));
    ull dap = pfma(dxp, q1.y, pfma(dyp, q2.x, pmul(dzp, q2.y)));   // delta . outdirL_i
    ull dbp = pfma(dxp, inx2, pfma(dyp, iny2, pmul(dzp, inz2)));   // delta . indirL_j

    float d20, d21; upk(d2p, d20, d21);
    float r0 = rsqrt_ap(fmaxf(d20, EPS));
    float r1 = rsqrt_ap(fmaxf(d21, EPS));
    ull rp = pk(r0, r1);

    ull ap = pmul(dap, rp);
    ull bp = pmul(dbp, rp);
    float av0, av1, bv0, bv1;
    upk(ap, av0, av1); upk(bp, bv0, bv1);

    ull eap = pk(ex2_ap(av0), ex2_ap(av1));
    ull ebp = pk(ex2_ap(bv0), ex2_ap(bv1));

    ull gp2 = pmul(padd(eap, cneg), padd(ebp, cneg));   // unnormalized gate pair
    float g0, g1; upk(gp2, g0, g1);
    ull gg0 = pk(g0, g0);
    ull gg1 = pk(g1, g1);

    a0 = pfma(Xa.x, gg0, a0);
    a1 = pfma(Xa.y, gg0, a1);
    a2 = pfma(Xb.x, gg0, a2);
    a3 = pfma(Xb.y, gg0, a3);
    a0 = pfma(Xc.x, gg1, a0);
    a1 = pfma(Xc.y, gg1, a1);
    a2 = pfma(Xd.x, gg1, a2);
    a3 = pfma(Xd.y, gg1, a3);
}

// -------- single fused kernel --------
__global__ void __launch_bounds__(JT, 12) fused_kernel(const float* __restrict__ x,
                                                       const float* __restrict__ pos,
                                                       const float* __restrict__ indir,
                                                       const float* __restrict__ outdir,
                                                       const float* __restrict__ power,
                                                       const float* __restrict__ bias,
                                                       float* __restrict__ out) {
    // i-side geometry, pair-SoA: per pair p (i=2p,2p+1):
    // [-px0,-px1, -py0,-py1, -pz0,-pz1, ox0,ox1, oy0,oy1, oz0,oz1]  (12 floats, 48B)
    __shared__ float sG[(ICH / 2) * 12];             // 1.5 KB
    __shared__ float sXf[ICH * 8];                   // xT tile: sXf[i*8+b], 2 KB
    __shared__ int s_last;

    const int tid   = threadIdx.x;
    const int jtile = blockIdx.x;
    const int chunk = blockIdx.y;
    const int i0    = chunk * ICH;
    const int j0    = jtile * JCOV + tid;
    const int j1    = j0 + JT;

    // ---- stage i-chunk (one i per thread), fused prep ----
    {
        const int i = i0 + tid;
        const int p = tid >> 1, h = tid & 1;
        float* gp_ = sG + p * 12;
        gp_[0  + h] = -pos[3 * i + 0];
        gp_[2  + h] = -pos[3 * i + 1];
        gp_[4  + h] = -pos[3 * i + 2];
        gp_[6  + h] = outdir[3 * i + 0] * LOG2E;
        gp_[8  + h] = outdir[3 * i + 1] * LOG2E;
        gp_[10 + h] = outdir[3 * i + 2] * LOG2E;
        #pragma unroll
        for (int b = 0; b < B; b++)
            sXf[tid * 8 + b] = x[b * N + i];
    }

    // ---- j-side registers for both owned j-columns ----
    const ull pjx2_0 = pk(pos[3 * j0 + 0], pos[3 * j0 + 0]);
    const ull pjy2_0 = pk(pos[3 * j0 + 1], pos[3 * j0 + 1]);
    const ull pjz2_0 = pk(pos[3 * j0 + 2], pos[3 * j0 + 2]);
    const float inx0 = indir[3 * j0 + 0] * LOG2E;
    const float iny0 = indir[3 * j0 + 1] * LOG2E;
    const float inz0 = indir[3 * j0 + 2] * LOG2E;
    const ull inx2_0 = pk(inx0, inx0), iny2_0 = pk(iny0, iny0), inz2_0 = pk(inz0, inz0);

    const ull pjx2_1 = pk(pos[3 * j1 + 0], pos[3 * j1 + 0]);
    const ull pjy2_1 = pk(pos[3 * j1 + 1], pos[3 * j1 + 1]);
    const ull pjz2_1 = pk(pos[3 * j1 + 2], pos[3 * j1 + 2]);
    const float inx1 = indir[3 * j1 + 0] * LOG2E;
    const float iny1 = indir[3 * j1 + 1] * LOG2E;
    const float inz1 = indir[3 * j1 + 2] * LOG2E;
    const ull inx2_1 = pk(inx1, inx1), iny2_1 = pk(iny1, iny1), inz2_1 = pk(inz1, inz1);

    const ull cneg = pk(-EXP_NEG1, -EXP_NEG1);

    __syncthreads();

    ull a00 = 0ull, a01 = 0ull, a02 = 0ull, a03 = 0ull;   // j0 accumulators
    ull a10 = 0ull, a11 = 0ull, a12 = 0ull, a13 = 0ull;   // j1 accumulators

    #pragma unroll 2
    for (int p = 0; p < ICH / 2; p++) {
        const ulonglong2* gq = reinterpret_cast<const ulonglong2*>(sG + p * 12);
        ulonglong2 q0 = gq[0];   // -posx pair | -posy pair
        ulonglong2 q1 = gq[1];   // -posz pair |  odx pair
        ulonglong2 q2 = gq[2];   //  ody pair  |  odz pair

        const ulonglong2* X0 = reinterpret_cast<const ulonglong2*>(sXf + (2 * p) * 8);
        ulonglong2 Xa = X0[0], Xb = X0[1];   // i = 2p : b0..3 | b4..7
        ulonglong2 Xc = X0[2], Xd = X0[3];   // i = 2p+1

        do_jcol(q0, q1, q2, Xa, Xb, Xc, Xd,
                pjx2_0, pjy2_0, pjz2_0, inx2_0, iny2_0, inz2_0, cneg,
                a00, a01, a02, a03);
        do_jcol(q0, q1, q2, Xa, Xb, Xc, Xd,
                pjx2_1, pjy2_1, pjz2_1, inx2_1, iny2_1, inz2_1, cneg,
                a10, a11, a12, a13);
    }

    // ---- write partials ----
    {
        ulonglong2* pp0 = reinterpret_cast<ulonglong2*>(&g_part[chunk][j0][0]);
        pp0[0] = make_ulonglong2(a00, a01);
        pp0[1] = make_ulonglong2(a02, a03);
        ulonglong2* pp1 = reinterpret_cast<ulonglong2*>(&g_part[chunk][j1][0]);
        pp1[0] = make_ulonglong2(a10, a11);
        pp1[1] = make_ulonglong2(a12, a13);
    }

    // ---- last-block-per-column reduction + epilogue ----
    __threadfence();
    __syncthreads();
    if (tid == 0)
        s_last = (atomicAdd(&g_cnt[jtile], 1) == NCHUNK - 1);
    __syncthreads();

    if (s_last) {
        #pragma unroll
        for (int jj = 0; jj < JB; jj++) {
            const int j = j0 + jj * JT;
            float s0 = 0.f, s1 = 0.f, s2 = 0.f, s3 = 0.f;
            float s4 = 0.f, s5 = 0.f, s6 = 0.f, s7 = 0.f;
            #pragma unroll 8
            for (int c = 0; c < NCHUNK; c++) {
                float4 a = __ldcg(&g_part[c][j][0]);
                float4 b = __ldcg(&g_part[c][j][1]);
                s0 += a.x; s1 += a.y; s2 += a.z; s3 += a.w;
                s4 += b.x; s5 += b.y; s6 += b.z; s7 += b.w;
            }
            float pw = power[j] * INV_D2;
            float bi = bias[j];
            float v;
            v = fmaf(s0, pw, -bi); out[0 * N + j] = v > 0.f ? v : expm1f(v);
            v = fmaf(s1, pw, -bi); out[1 * N + j] = v > 0.f ? v : expm1f(v);
            v = fmaf(s2, pw, -bi); out[2 * N + j] = v > 0.f ? v : expm1f(v);
            v = fmaf(s3, pw, -bi); out[3 * N + j] = v > 0.f ? v : expm1f(v);
            v = fmaf(s4, pw, -bi); out[4 * N + j] = v > 0.f ? v : expm1f(v);
            v = fmaf(s5, pw, -bi); out[5 * N + j] = v > 0.f ? v : expm1f(v);
            v = fmaf(s6, pw, -bi); out[6 * N + j] = v > 0.f ? v : expm1f(v);
            v = fmaf(s7, pw, -bi); out[7 * N + j] = v > 0.f ? v : expm1f(v);
        }
        if (tid == 0) g_cnt[jtile] = 0;   // reset for next graph replay
    }
}

extern "C" void kernel_launch(void* const* d_in, const int* in_sizes, int n_in,
                              void* d_out, int out_size) {
    const float* x      = (const float*)d_in[0];
    const float* pos    = (const float*)d_in[1];
    const float* indir  = (const float*)d_in[2];
    const float* outdir = (const float*)d_in[3];
    const float* power  = (const float*)d_in[4];
    const float* bias   = (const float*)d_in[5];
    float* out = (float*)d_out;

    dim3 grid(NJT, NCHUNK);
    fused_kernel<<<grid, JT>>>(x, pos, indir, outdir, power, bias, out);
}

// round 11
// speedup vs baseline: 1.1009x; 1.1009x over previous
#include <cuda_runtime.h>

#define N 4096
#define B 8
#define JT 128             // threads per block
#define ICH 64             // i per chunk
#define NCHUNK (N / ICH)   // 64
#define NJT (N / JT)       // 32

#define LOG2E 1.4426950408889634f
#define EXP_NEG1 0.36787944117144233f
#define DVAL 2.3504023872876028f
#define INV_D2 (1.0f / (DVAL * DVAL))
#define EPS 1e-5f

typedef unsigned long long ull;

// -------- packed f32x2 helpers --------
__device__ __forceinline__ ull pk(float lo, float hi) {
    ull r; asm("mov.b64 %0, {%1, %2};" : "=l"(r) : "f"(lo), "f"(hi)); return r;
}
__device__ __forceinline__ void upk(ull v, float& lo, float& hi) {
    asm("mov.b64 {%0, %1}, %2;" : "=f"(lo), "=f"(hi) : "l"(v));
}
__device__ __forceinline__ ull padd(ull a, ull b) {
    ull r; asm("add.rn.f32x2 %0, %1, %2;" : "=l"(r) : "l"(a), "l"(b)); return r;
}
__device__ __forceinline__ ull pmul(ull a, ull b) {
    ull r; asm("mul.rn.f32x2 %0, %1, %2;" : "=l"(r) : "l"(a), "l"(b)); return r;
}
__device__ __forceinline__ ull pfma(ull a, ull b, ull c) {
    ull r; asm("fma.rn.f32x2 %0, %1, %2, %3;" : "=l"(r) : "l"(a), "l"(b), "l"(c)); return r;
}
__device__ __forceinline__ float rsqrt_ap(float v) {
    float r; asm("rsqrt.approx.f32 %0, %1;" : "=f"(r) : "f"(v)); return r;
}
__device__ __forceinline__ float ex2_ap(float v) {
    float r; asm("ex2.approx.ftz.f32 %0, %1;" : "=f"(r) : "f"(v)); return r;
}

// -------- device scratch (no allocations allowed) --------
__device__ float4 g_part[NCHUNK][N][2];   // partial sums [chunk][j] -> 8 floats
__device__ int g_cnt[NJT];                // arrival counters (zero-init)

// -------- single fused kernel --------
__global__ void __launch_bounds__(JT, 8) fused_kernel(const float* __restrict__ x,
                                                      const float* __restrict__ pos,
                                                      const float* __restrict__ indir,
                                                      const float* __restrict__ outdir,
                                                      const float* __restrict__ power,
                                                      const float* __restrict__ bias,
                                                      float* __restrict__ out) {
    // i-side geometry, pair-SoA: per pair p (i=2p,2p+1):
    // [-px0,-px1, -py0,-py1, -pz0,-pz1, ox0,ox1, oy0,oy1, oz0,oz1]
    __shared__ float sG[(ICH / 2) * 12];             // 1.5 KB
    __shared__ float sXf[ICH * 8];                   // xT tile: sXf[i*8+b], 2 KB
    __shared__ int s_last;

    const int tid   = threadIdx.x;
    const int jtile = blockIdx.x;
    const int chunk = blockIdx.y;
    const int i0    = chunk * ICH;
    const int j     = jtile * JT + tid;

    // ---- stage i-chunk, fused prep ----
    if (tid < ICH) {
        const int i = i0 + tid;
        const int p = tid >> 1, h = tid & 1;
        float* gp_ = sG + p * 12;
        gp_[0  + h] = -pos[3 * i + 0];
        gp_[2  + h] = -pos[3 * i + 1];
        gp_[4  + h] = -pos[3 * i + 2];
        gp_[6  + h] = outdir[3 * i + 0] * LOG2E;
        gp_[8  + h] = outdir[3 * i + 1] * LOG2E;
        gp_[10 + h] = outdir[3 * i + 2] * LOG2E;
    }
    {
        // x transpose stage: threads 0-63 do b=0..3, threads 64-127 do b=4..7
        const int ii = tid & (ICH - 1);
        const int b0 = (tid >> 6) * 4;
        #pragma unroll
        for (int b = b0; b < b0 + 4; b++)
            sXf[ii * 8 + b] = x[b * N + i0 + ii];
    }

    // ---- j-side registers (packed broadcasts) ----
    const ull pjx2 = pk(pos[3 * j + 0], pos[3 * j + 0]);
    const ull pjy2 = pk(pos[3 * j + 1], pos[3 * j + 1]);
    const ull pjz2 = pk(pos[3 * j + 2], pos[3 * j + 2]);
    const float inx = indir[3 * j + 0] * LOG2E;
    const float iny = indir[3 * j + 1] * LOG2E;
    const float inz = indir[3 * j + 2] * LOG2E;
    const ull inx2 = pk(inx, inx), iny2 = pk(iny, iny), inz2 = pk(inz, inz);
    const ull cneg = pk(-EXP_NEG1, -EXP_NEG1);

    __syncthreads();

    ull acc0 = 0ull, acc1 = 0ull, acc2 = 0ull, acc3 = 0ull;

    // ---- main loop: 2 independent i-pair streams per body (4 i's) ----
    #pragma unroll 2
    for (int p = 0; p < ICH / 2; p += 2) {
        // --- load both streams up front (broadcast LDS) ---
        const ulonglong2* gqA = reinterpret_cast<const ulonglong2*>(sG + p * 12);
        const ulonglong2* gqB = reinterpret_cast<const ulonglong2*>(sG + (p + 1) * 12);
        ulonglong2 qA0 = gqA[0], qA1 = gqA[1], qA2 = gqA[2];
        ulonglong2 qB0 = gqB[0], qB1 = gqB[1], qB2 = gqB[2];

        // --- geometry chains, interleaved ---
        ull dxA = padd(pjx2, qA0.x);
        ull dxB = padd(pjx2, qB0.x);
        ull dyA = padd(pjy2, qA0.y);
        ull dyB = padd(pjy2, qB0.y);
        ull dzA = padd(pjz2, qA1.x);
        ull dzB = padd(pjz2, qB1.x);

        ull d2A = pfma(dxA, dxA, pfma(dyA, dyA, pmul(dzA, dzA)));
        ull d2B = pfma(dxB, dxB, pfma(dyB, dyB, pmul(dzB, dzB)));
        ull daA = pfma(dxA, qA1.y, pfma(dyA, qA2.x, pmul(dzA, qA2.y)));
        ull daB = pfma(dxB, qB1.y, pfma(dyB, qB2.x, pmul(dzB, qB2.y)));
        ull dbA = pfma(dxA, inx2, pfma(dyA, iny2, pmul(dzA, inz2)));
        ull dbB = pfma(dxB, inx2, pfma(dyB, iny2, pmul(dzB, inz2)));

        float d2A0, d2A1, d2B0, d2B1;
        upk(d2A, d2A0, d2A1); upk(d2B, d2B0, d2B1);
        float rA0 = rsqrt_ap(fmaxf(d2A0, EPS));
        float rA1 = rsqrt_ap(fmaxf(d2A1, EPS));
        float rB0 = rsqrt_ap(fmaxf(d2B0, EPS));
        float rB1 = rsqrt_ap(fmaxf(d2B1, EPS));
        ull rA = pk(rA0, rA1);
        ull rB = pk(rB0, rB1);

        ull apA = pmul(daA, rA);
        ull apB = pmul(daB, rB);
        ull bpA = pmul(dbA, rA);
        ull bpB = pmul(dbB, rB);

        float aA0, aA1, bA0, bA1, aB0, aB1, bB0, bB1;
        upk(apA, aA0, aA1); upk(bpA, bA0, bA1);
        upk(apB, aB0, aB1); upk(bpB, bB0, bB1);

        ull eaA = pk(ex2_ap(aA0), ex2_ap(aA1));
        ull ebA = pk(ex2_ap(bA0), ex2_ap(bA1));
        ull eaB = pk(ex2_ap(aB0), ex2_ap(aB1));
        ull ebB = pk(ex2_ap(bB0), ex2_ap(bB1));

        ull gA = pmul(padd(eaA, cneg), padd(ebA, cneg));
        ull gB = pmul(padd(eaB, cneg), padd(ebB, cneg));

        float gA0, gA1, gB0, gB1;
        upk(gA, gA0, gA1); upk(gB, gB0, gB1);
        ull ggA0 = pk(gA0, gA0), ggA1 = pk(gA1, gA1);
        ull ggB0 = pk(gB0, gB0), ggB1 = pk(gB1, gB1);

        // --- accumulate (4 i's) ---
        const ulonglong2* XA = reinterpret_cast<const ulonglong2*>(sXf + (2 * p) * 8);
        ulonglong2 XAa = XA[0], XAb = XA[1];   // i = 2p
        ulonglong2 XAc = XA[2], XAd = XA[3];   // i = 2p+1
        ulonglong2 XBa = XA[4], XBb = XA[5];   // i = 2p+2
        ulonglong2 XBc = XA[6], XBd = XA[7];   // i = 2p+3

        acc0 = pfma(XAa.x, ggA0, acc0);
        acc1 = pfma(XAa.y, ggA0, acc1);
        acc2 = pfma(XAb.x, ggA0, acc2);
        acc3 = pfma(XAb.y, ggA0, acc3);
        acc0 = pfma(XAc.x, ggA1, acc0);
        acc1 = pfma(XAc.y, ggA1, acc1);
        acc2 = pfma(XAd.x, ggA1, acc2);
        acc3 = pfma(XAd.y, ggA1, acc3);
        acc0 = pfma(XBa.x, ggB0, acc0);
        acc1 = pfma(XBa.y, ggB0, acc1);
        acc2 = pfma(XBb.x, ggB0, acc2);
        acc3 = pfma(XBb.y, ggB0, acc3);
        acc0 = pfma(XBc.x, ggB1, acc0);
        acc1 = pfma(XBc.y, ggB1, acc1);
        acc2 = pfma(XBd.x, ggB1, acc2);
        acc3 = pfma(XBd.y, ggB1, acc3);
    }

    // ---- write partials ----
    ulonglong2* pp = reinterpret_cast<ulonglong2*>(&g_part[chunk][j][0]);
    pp[0] = make_ulonglong2(acc0, acc1);
    pp[1] = make_ulonglong2(acc2, acc3);

    // ---- last-block-per-column reduction + epilogue ----
    __threadfence();
    __syncthreads();
    if (tid == 0)
        s_last = (atomicAdd(&g_cnt[jtile], 1) == NCHUNK - 1);
    __syncthreads();

    if (s_last) {
        float s0 = 0.f, s1 = 0.f, s2 = 0.f, s3 = 0.f;
        float s4 = 0.f, s5 = 0.f, s6 = 0.f, s7 = 0.f;
        #pragma unroll 8
        for (int c = 0; c < NCHUNK; c++) {
            float4 a = __ldcg(&g_part[c][j][0]);
            float4 b = __ldcg(&g_part[c][j][1]);
            s0 += a.x; s1 += a.y; s2 += a.z; s3 += a.w;
            s4 += b.x; s5 += b.y; s6 += b.z; s7 += b.w;
        }
        float pw = power[j] * INV_D2;
        float bi = bias[j];
        float v;
        v = fmaf(s0, pw, -bi); out[0 * N + j] = v > 0.f ? v : expm1f(v);
        v = fmaf(s1, pw, -bi); out[1 * N + j] = v > 0.f ? v : expm1f(v);
        v = fmaf(s2, pw, -bi); out[2 * N + j] = v > 0.f ? v : expm1f(v);
        v = fmaf(s3, pw, -bi); out[3 * N + j] = v > 0.f ? v : expm1f(v);
        v = fmaf(s4, pw, -bi); out[4 * N + j] = v > 0.f ? v : expm1f(v);
        v = fmaf(s5, pw, -bi); out[5 * N + j] = v > 0.f ? v : expm1f(v);
        v = fmaf(s6, pw, -bi); out[6 * N + j] = v > 0.f ? v : expm1f(v);
        v = fmaf(s7, pw, -bi); out[7 * N + j] = v > 0.f ? v : expm1f(v);
        if (tid == 0) g_cnt[jtile] = 0;   // reset for next graph replay
    }
}

extern "C" void kernel_launch(void* const* d_in, const int* in_sizes, int n_in,
                              void* d_out, int out_size) {
    const float* x      = (const float*)d_in[0];
    const float* pos    = (const float*)d_in[1];
    const float* indir  = (const float*)d_in[2];
    const float* outdir = (const float*)d_in[3];
    const float* power  = (const float*)d_in[4];
    const float* bias   = (const float*)d_in[5];
    float* out = (float*)d_out;

    dim3 grid(NJT, NCHUNK);
    fused_kernel<<<grid, JT>>>(x, pos, indir, outdir, power, bias, out);
}

// round 15
// speedup vs baseline: 1.2347x; 1.1215x over previous
#include <cuda_runtime.h>

#define N 4096
#define B 8
#define JT 128             // threads per block
#define ICH 64             // i per chunk
#define NCHUNK (N / ICH)   // 64
#define NJT (N / JT)       // 32

#define LOG2E 1.4426950408889634f
#define EXP_NEG1 0.36787944117144233f
#define DVAL 2.3504023872876028f
#define INV_D2 (1.0f / (DVAL * DVAL))
#define EPS 1e-5f

typedef unsigned long long ull;

// -------- packed f32x2 helpers --------
__device__ __forceinline__ ull pk(float lo, float hi) {
    ull r; asm("mov.b64 %0, {%1, %2};" : "=l"(r) : "f"(lo), "f"(hi)); return r;
}
__device__ __forceinline__ void upk(ull v, float& lo, float& hi) {
    asm("mov.b64 {%0, %1}, %2;" : "=f"(lo), "=f"(hi) : "l"(v));
}
__device__ __forceinline__ ull padd(ull a, ull b) {
    ull r; asm("add.rn.f32x2 %0, %1, %2;" : "=l"(r) : "l"(a), "l"(b)); return r;
}
__device__ __forceinline__ ull pmul(ull a, ull b) {
    ull r; asm("mul.rn.f32x2 %0, %1, %2;" : "=l"(r) : "l"(a), "l"(b)); return r;
}
__device__ __forceinline__ ull pfma(ull a, ull b, ull c) {
    ull r; asm("fma.rn.f32x2 %0, %1, %2, %3;" : "=l"(r) : "l"(a), "l"(b), "l"(c)); return r;
}
__device__ __forceinline__ float rsqrt_ap(float v) {
    float r; asm("rsqrt.approx.f32 %0, %1;" : "=f"(r) : "f"(v)); return r;
}
__device__ __forceinline__ float ex2_ap(float v) {
    float r; asm("ex2.approx.ftz.f32 %0, %1;" : "=f"(r) : "f"(v)); return r;
}

// -------- device scratch (no allocations allowed) --------
__device__ float4 g_part[NCHUNK][N][2];   // partial sums [chunk][j] -> 8 floats
__device__ int g_cnt[NJT];                // arrival counters (zero-init)

// -------- single fused kernel --------
__global__ void __launch_bounds__(JT, 5) fused_kernel(const float* __restrict__ x,
                                                      const float* __restrict__ pos,
                                                      const float* __restrict__ indir,
                                                      const float* __restrict__ outdir,
                                                      const float* __restrict__ power,
                                                      const float* __restrict__ bias,
                                                      float* __restrict__ out) {
    // i-side geometry, pair-SoA: per pair p (i=2p,2p+1):
    // [-px0,-px1, -py0,-py1, -pz0,-pz1, ox0,ox1, oy0,oy1, oz0,oz1]
    __shared__ float sG[(ICH / 2) * 12];             // 1.5 KB
    __shared__ float sXf[ICH * 8];                   // xT tile: sXf[i*8+b], 2 KB
    __shared__ int s_last;

    const int tid   = threadIdx.x;
    const int jtile = blockIdx.x;
    const int chunk = blockIdx.y;
    const int i0    = chunk * ICH;
    const int j     = jtile * JT + tid;

    // ---- stage i-chunk, fused prep ----
    if (tid < ICH) {
        const int i = i0 + tid;
        const int p = tid >> 1, h = tid & 1;
        float* gp_ = sG + p * 12;
        gp_[0  + h] = -pos[3 * i + 0];
        gp_[2  + h] = -pos[3 * i + 1];
        gp_[4  + h] = -pos[3 * i + 2];
        gp_[6  + h] = outdir[3 * i + 0] * LOG2E;
        gp_[8  + h] = outdir[3 * i + 1] * LOG2E;
        gp_[10 + h] = outdir[3 * i + 2] * LOG2E;
    }
    {
        // x transpose stage: threads 0-63 do b=0..3, threads 64-127 do b=4..7
        const int ii = tid & (ICH - 1);
        const int b0 = (tid >> 6) * 4;
        #pragma unroll
        for (int b = b0; b < b0 + 4; b++)
            sXf[ii * 8 + b] = x[b * N + i0 + ii];
    }

    // ---- j-side registers (packed broadcasts) ----
    const ull pjx2 = pk(pos[3 * j + 0], pos[3 * j + 0]);
    const ull pjy2 = pk(pos[3 * j + 1], pos[3 * j + 1]);
    const ull pjz2 = pk(pos[3 * j + 2], pos[3 * j + 2]);
    const float inx = indir[3 * j + 0] * LOG2E;
    const float iny = indir[3 * j + 1] * LOG2E;
    const float inz = indir[3 * j + 2] * LOG2E;
    const ull inx2 = pk(inx, inx), iny2 = pk(iny, iny), inz2 = pk(inz, inz);
    const ull cneg = pk(-EXP_NEG1, -EXP_NEG1);

    __syncthreads();

    ull acc0 = 0ull, acc1 = 0ull, acc2 = 0ull, acc3 = 0ull;

    // ---- main loop: 2 independent i-pair streams per body (4 i's) ----
    #pragma unroll 2
    for (int p = 0; p < ICH / 2; p += 2) {
        // --- load both streams up front (broadcast LDS) ---
        const ulonglong2* gqA = reinterpret_cast<const ulonglong2*>(sG + p * 12);
        const ulonglong2* gqB = reinterpret_cast<const ulonglong2*>(sG + (p + 1) * 12);
        ulonglong2 qA0 = gqA[0], qA1 = gqA[1], qA2 = gqA[2];
        ulonglong2 qB0 = gqB[0], qB1 = gqB[1], qB2 = gqB[2];

        // --- geometry chains, interleaved ---
        ull dxA = padd(pjx2, qA0.x);
        ull dxB = padd(pjx2, qB0.x);
        ull dyA = padd(pjy2, qA0.y);
        ull dyB = padd(pjy2, qB0.y);
        ull dzA = padd(pjz2, qA1.x);
        ull dzB = padd(pjz2, qB1.x);

        ull d2A = pfma(dxA, dxA, pfma(dyA, dyA, pmul(dzA, dzA)));
        ull d2B = pfma(dxB, dxB, pfma(dyB, dyB, pmul(dzB, dzB)));
        ull daA = pfma(dxA, qA1.y, pfma(dyA, qA2.x, pmul(dzA, qA2.y)));
        ull daB = pfma(dxB, qB1.y, pfma(dyB, qB2.x, pmul(dzB, qB2.y)));
        ull dbA = pfma(dxA, inx2, pfma(dyA, iny2, pmul(dzA, inz2)));
        ull dbB = pfma(dxB, inx2, pfma(dyB, iny2, pmul(dzB, inz2)));

        float d2A0, d2A1, d2B0, d2B1;
        upk(d2A, d2A0, d2A1); upk(d2B, d2B0, d2B1);
        float rA0 = rsqrt_ap(fmaxf(d2A0, EPS));
        float rA1 = rsqrt_ap(fmaxf(d2A1, EPS));
        float rB0 = rsqrt_ap(fmaxf(d2B0, EPS));
        float rB1 = rsqrt_ap(fmaxf(d2B1, EPS));
        ull rA = pk(rA0, rA1);
        ull rB = pk(rB0, rB1);

        ull apA = pmul(daA, rA);
        ull apB = pmul(daB, rB);
        ull bpA = pmul(dbA, rA);
        ull bpB = pmul(dbB, rB);

        float aA0, aA1, bA0, bA1, aB0, aB1, bB0, bB1;
        upk(apA, aA0, aA1); upk(bpA, bA0, bA1);
        upk(apB, aB0, aB1); upk(bpB, bB0, bB1);

        ull eaA = pk(ex2_ap(aA0), ex2_ap(aA1));
        ull ebA = pk(ex2_ap(bA0), ex2_ap(bA1));
        ull eaB = pk(ex2_ap(aB0), ex2_ap(aB1));
        ull ebB = pk(ex2_ap(bB0), ex2_ap(bB1));

        ull gA = pmul(padd(eaA, cneg), padd(ebA, cneg));
        ull gB = pmul(padd(eaB, cneg), padd(ebB, cneg));

        float gA0, gA1, gB0, gB1;
        upk(gA, gA0, gA1); upk(gB, gB0, gB1);
        ull ggA0 = pk(gA0, gA0), ggA1 = pk(gA1, gA1);
        ull ggB0 = pk(gB0, gB0), ggB1 = pk(gB1, gB1);

        // --- accumulate (4 i's) ---
        const ulonglong2* XA = reinterpret_cast<const ulonglong2*>(sXf + (2 * p) * 8);
        ulonglong2 XAa = XA[0], XAb = XA[1];   // i = 2p
        ulonglong2 XAc = XA[2], XAd = XA[3];   // i = 2p+1
        ulonglong2 XBa = XA[4], XBb = XA[5];   // i = 2p+2
        ulonglong2 XBc = XA[6], XBd = XA[7];   // i = 2p+3

        acc0 = pfma(XAa.x, ggA0, acc0);
        acc1 = pfma(XAa.y, ggA0, acc1);
        acc2 = pfma(XAb.x, ggA0, acc2);
        acc3 = pfma(XAb.y, ggA0, acc3);
        acc0 = pfma(XAc.x, ggA1, acc0);
        acc1 = pfma(XAc.y, ggA1, acc1);
        acc2 = pfma(XAd.x, ggA1, acc2);
        acc3 = pfma(XAd.y, ggA1, acc3);
        acc0 = pfma(XBa.x, ggB0, acc0);
        acc1 = pfma(XBa.y, ggB0, acc1);
        acc2 = pfma(XBb.x, ggB0, acc2);
        acc3 = pfma(XBb.y, ggB0, acc3);
        acc0 = pfma(XBc.x, ggB1, acc0);
        acc1 = pfma(XBc.y, ggB1, acc1);
        acc2 = pfma(XBd.x, ggB1, acc2);
        acc3 = pfma(XBd.y, ggB1, acc3);
    }

    // ---- write partials ----
    ulonglong2* pp = reinterpret_cast<ulonglong2*>(&g_part[chunk][j][0]);
    pp[0] = make_ulonglong2(acc0, acc1);
    pp[1] = make_ulonglong2(acc2, acc3);

    // ---- last-block-per-column reduction + epilogue ----
    __threadfence();
    __syncthreads();
    if (tid == 0)
        s_last = (atomicAdd(&g_cnt[jtile], 1) == NCHUNK - 1);
    __syncthreads();

    if (s_last) {
        float s0 = 0.f, s1 = 0.f, s2 = 0.f, s3 = 0.f;
        float s4 = 0.f, s5 = 0.f, s6 = 0.f, s7 = 0.f;
        #pragma unroll 8
        for (int c = 0; c < NCHUNK; c++) {
            float4 a = __ldcg(&g_part[c][j][0]);
            float4 b = __ldcg(&g_part[c][j][1]);
            s0 += a.x; s1 += a.y; s2 += a.z; s3 += a.w;
            s4 += b.x; s5 += b.y; s6 += b.z; s7 += b.w;
        }
        float pw = power[j] * INV_D2;
        float bi = bias[j];
        float v;
        v = fmaf(s0, pw, -bi); out[0 * N + j] = v > 0.f ? v : expm1f(v);
        v = fmaf(s1, pw, -bi); out[1 * N + j] = v > 0.f ? v : expm1f(v);
        v = fmaf(s2, pw, -bi); out[2 * N + j] = v > 0.f ? v : expm1f(v);
        v = fmaf(s3, pw, -bi); out[3 * N + j] = v > 0.f ? v : expm1f(v);
        v = fmaf(s4, pw, -bi); out[4 * N + j] = v > 0.f ? v : expm1f(v);
        v = fmaf(s5, pw, -bi); out[5 * N + j] = v > 0.f ? v : expm1f(v);
        v = fmaf(s6, pw, -bi); out[6 * N + j] = v > 0.f ? v : expm1f(v);
        v = fmaf(s7, pw, -bi); out[7 * N + j] = v > 0.f ? v : expm1f(v);
        if (tid == 0) g_cnt[jtile] = 0;   // reset for next graph replay
    }
}

extern "C" void kernel_launch(void* const* d_in, const int* in_sizes, int n_in,
                              void* d_out, int out_size) {
    const float* x      = (const float*)d_in[0];
    const float* pos    = (const float*)d_in[1];
    const float* indir  = (const float*)d_in[2];
    const float* outdir = (const float*)d_in[3];
    const float* power  = (const float*)d_in[4];
    const float* bias   = (const float*)d_in[5];
    float* out = (float*)d_out;

    dim3 grid(NJT, NCHUNK);
    fused_kernel<<<grid, JT>>>(x, pos, indir, outdir, power, bias, out);
}